// round 14
// baseline (speedup 1.0000x reference)
#include <cuda_runtime.h>
#include <cuda_bf16.h>
#include <cstdint>

#define HID 256
#define AH  32
#define NU  10000
#define NI  30000
#define NN  40000
#define NE  500000
#define THRESH 0.8f

#define MBLKS 313            // ceil(NN/128)
#define TB    10240          // one tile: 128 rows x 80 B
#define SPLIT_MAIN 104       // M-blocks run on the main stream (rest on s2)

typedef unsigned long long ull;

// ---------------- device scratch ----------------
__device__ float g_UW1[NU * AH];
__device__ float g_IW1[NI * AH];
__device__ float g_w[NE];
__device__ float g_xw[(size_t)NN * HID];
__device__ float g_dinv[NN];
__device__ int   g_cnt[NN];
__device__ int   g_off[NN];
__device__ int   g_cur[NN];
__device__ int   g_srcl[NE];
__device__ float g_coef[NE];
__device__ ull   g_amax;
__device__ int   g_kept;
// tile-blocked bf16 hi/lo operands: [blk][kchunk(8)][128 rows][80 B]
__device__ __align__(128) unsigned char g_XhiT[(size_t)MBLKS * 8 * TB];
__device__ __align__(128) unsigned char g_XloT[(size_t)MBLKS * 8 * TB];
__device__ __align__(128) unsigned char g_BhiT[2 * 8 * TB];
__device__ __align__(128) unsigned char g_BloT[2 * 8 * TB];

// ---------------- helpers ----------------
__device__ __forceinline__ uint32_t s2u(const void* p) {
    uint32_t a;
    asm("{ .reg .u64 t; cvta.to.shared.u64 t, %1; cvt.u32.u64 %0, t; }" : "=r"(a) : "l"(p));
    return a;
}
__device__ __forceinline__ void ldsm4(uint32_t* r, uint32_t addr) {
    asm volatile("ldmatrix.sync.aligned.m8n8.x4.shared.b16 {%0,%1,%2,%3}, [%4];"
                 : "=r"(r[0]), "=r"(r[1]), "=r"(r[2]), "=r"(r[3]) : "r"(addr));
}
__device__ __forceinline__ void mma16816(float* c, const uint32_t* a, const uint32_t* b) {
    asm volatile("mma.sync.aligned.m16n8k16.row.col.f32.bf16.bf16.f32 "
                 "{%0,%1,%2,%3}, {%4,%5,%6,%7}, {%8,%9}, {%0,%1,%2,%3};"
                 : "+f"(c[0]), "+f"(c[1]), "+f"(c[2]), "+f"(c[3])
                 : "r"(a[0]), "r"(a[1]), "r"(a[2]), "r"(a[3]), "r"(b[0]), "r"(b[1]));
}
__device__ __forceinline__ ull pk2(float x, float y) {
    ull r; asm("mov.b64 %0, {%1, %2};" : "=l"(r) : "f"(x), "f"(y)); return r;
}
__device__ __forceinline__ void ffma2(ull& d, ull a, ull b) {
    asm("fma.rn.f32x2 %0, %1, %2, %0;" : "+l"(d) : "l"(a), "l"(b));
}
__device__ __forceinline__ void bulk_ld(uint32_t dst, const void* src, uint32_t bytes, uint32_t mbar) {
    asm volatile("cp.async.bulk.shared::cluster.global.mbarrier::complete_tx::bytes "
                 "[%0], [%1], %2, [%3];"
                 :: "r"(dst), "l"(src), "r"(bytes), "r"(mbar) : "memory");
}
__device__ __forceinline__ void mbar_init(uint32_t a, uint32_t cnt) {
    asm volatile("mbarrier.init.shared.b64 [%0], %1;" :: "r"(a), "r"(cnt) : "memory");
}
__device__ __forceinline__ void mbar_expect(uint32_t a, uint32_t bytes) {
    asm volatile("mbarrier.arrive.expect_tx.shared.b64 _, [%0], %1;" :: "r"(a), "r"(bytes) : "memory");
}
__device__ __forceinline__ void mbar_wait(uint32_t a, uint32_t par) {
    asm volatile(
        "{ .reg .pred P;\n"
        "W%=: mbarrier.try_wait.parity.acquire.cta.shared::cta.b64 P, [%0], %1, 0x989680;\n"
        "@P bra D%=; bra W%=; D%=: }"
        :: "r"(a), "r"(par) : "memory");
}

// ---------------- K0: reset ----------------
__global__ void k_init() {
    int i = blockIdx.x * blockDim.x + threadIdx.x;
    if (i < NN) g_cnt[i] = 0;
    if (i == 0) { g_amax = 0ULL; g_kept = 0; }
}

// ---------------- prepW: transpose + bf16 hi/lo split into tiled layout -------
__global__ void k_prepW(const float* __restrict__ W) {
    int i = blockIdx.x * blockDim.x + threadIdx.x;   // 65536
    int n = i & 255, k = i >> 8;
    float v = W[k * HID + n];
    __nv_bfloat16 h = __float2bfloat16(v);
    __nv_bfloat16 l = __float2bfloat16(v - __bfloat162float(h));
    int nblk = n >> 7, r = n & 127, kc = k >> 5, col = k & 31;
    size_t off = ((size_t)(nblk * 8 + kc) * 128 + r) * 80 + col * 2;
    *(__nv_bfloat16*)(g_BhiT + off) = h;
    *(__nv_bfloat16*)(g_BloT + off) = l;
}

// ---------------- prepX: bf16 hi/lo split of concat(U,I) into tiled layout ----
__global__ void k_prepX(const float* __restrict__ U, const float* __restrict__ I) {
    size_t i = ((size_t)blockIdx.x * 256 + threadIdx.x) * 4;   // grid 10000 exact
    int m = (int)(i >> 8), k = (int)(i & 255);
    const float* x = (m < NU) ? U + (size_t)m * HID : I + (size_t)(m - NU) * HID;
    float4 v = *(const float4*)(x + k);
    __nv_bfloat16 h0 = __float2bfloat16(v.x), h1 = __float2bfloat16(v.y);
    __nv_bfloat16 h2 = __float2bfloat16(v.z), h3 = __float2bfloat16(v.w);
    __nv_bfloat16 l0 = __float2bfloat16(v.x - __bfloat162float(h0));
    __nv_bfloat16 l1 = __float2bfloat16(v.y - __bfloat162float(h1));
    __nv_bfloat16 l2 = __float2bfloat16(v.z - __bfloat162float(h2));
    __nv_bfloat16 l3 = __float2bfloat16(v.w - __bfloat162float(h3));
    __nv_bfloat162 hp0, hp1, lp0, lp1;
    hp0.x = h0; hp0.y = h1; hp1.x = h2; hp1.y = h3;
    lp0.x = l0; lp0.y = l1; lp1.x = l2; lp1.y = l3;
    int mblk = m >> 7, r = m & 127, kc = k >> 5, col = k & 31;
    size_t off = ((size_t)(mblk * 8 + kc) * 128 + r) * 80 + col * 2;
    *(uint2*)(g_XhiT + off) = make_uint2(*(uint32_t*)&hp0, *(uint32_t*)&hp1);
    *(uint2*)(g_XloT + off) = make_uint2(*(uint32_t*)&lp0, *(uint32_t*)&lp1);
}

// ---------------- K1: merged node projection, f32x2 packed, 64-row tiles -----
#define UB2 ((NU + 63) / 64)   // 157
#define IB2 ((NI + 63) / 64)   // 469
__global__ void k_projB(const float* __restrict__ U, const float* __restrict__ I,
                        const float* __restrict__ W1, const float* __restrict__ b1) {
    __shared__ float Xs[32][66];
    __shared__ float Ws[32][32];
    const float* X; const float* Wp; const float* bv; float* P;
    int nrows, m0;
    if (blockIdx.x < UB2) {
        X = U;  Wp = W1;            bv = b1;      P = g_UW1; nrows = NU;
        m0 = blockIdx.x * 64;
    } else {
        X = I;  Wp = W1 + HID * AH; bv = nullptr; P = g_IW1; nrows = NI;
        m0 = (blockIdx.x - UB2) * 64;
    }
    int tid = threadIdx.x;
    int tr = tid >> 4, tc = tid & 15;
    ull acc[2][2] = {};
    for (int kc = 0; kc < HID; kc += 32) {
        if (kc) __syncthreads();
        for (int i = tid; i < 512; i += 256) {
            int r = i >> 3, q = i & 7;
            int m = m0 + r; if (m >= nrows) m = nrows - 1;
            float4 v = *(const float4*)(X + (size_t)m * HID + kc + q * 4);
            Xs[q*4+0][r] = v.x; Xs[q*4+1][r] = v.y;
            Xs[q*4+2][r] = v.z; Xs[q*4+3][r] = v.w;
        }
        {
            int r = tid >> 3, q = tid & 7;
            *(float4*)&Ws[r][q * 4] = *(const float4*)(Wp + (size_t)(kc + r) * AH + q * 4);
        }
        __syncthreads();
        #pragma unroll
        for (int k = 0; k < 32; k++) {
            ull a0 = *(const ull*)&Xs[k][tr * 4 + 0];
            ull a1 = *(const ull*)&Xs[k][tr * 4 + 2];
            float2 bw = *(const float2*)&Ws[k][tc * 2];
            ull b0 = pk2(bw.x, bw.x), b1v = pk2(bw.y, bw.y);
            ffma2(acc[0][0], a0, b0); ffma2(acc[0][1], a0, b1v);
            ffma2(acc[1][0], a1, b0); ffma2(acc[1][1], a1, b1v);
        }
    }
    float bb0 = bv ? bv[tc * 2] : 0.f, bb1 = bv ? bv[tc * 2 + 1] : 0.f;
    #pragma unroll
    for (int p = 0; p < 2; p++) {
        float2 c0 = *(float2*)&acc[p][0];
        float2 c1 = *(float2*)&acc[p][1];
        int r0 = m0 + tr * 4 + 2 * p;
        if (r0 < nrows)
            *(float2*)&P[(size_t)r0 * AH + tc * 2] = make_float2(c0.x + bb0, c1.x + bb1);
        if (r0 + 1 < nrows)
            *(float2*)&P[(size_t)(r0 + 1) * AH + tc * 2] = make_float2(c0.y + bb0, c1.y + bb1);
    }
}

// ---------------- K2: edge attention (8 lanes per edge) ----------------
__global__ void k_edge(const int* __restrict__ ei, const float* __restrict__ W2,
                       const float* __restrict__ b2, int E) {
    __shared__ float sW2[AH];
    __shared__ ull   blkmax;
    __shared__ int   blkkept;
    int tid = threadIdx.x;
    if (tid < AH) sW2[tid] = W2[tid];
    if (tid == 0) { blkmax = 0ULL; blkkept = 0; }
    __syncthreads();

    int lane = tid & 31;
    int gw = (blockIdx.x * blockDim.x + tid) >> 5;
    int sub = lane >> 3, part = lane & 7;
    int e = gw * 4 + sub;
    bool valid = e < E;
    int s = 0, d = 0;
    if (valid) { s = ei[e]; d = ei[E + e]; }

    float4 a = *(const float4*)(g_UW1 + (size_t)s * AH + part * 4);
    float4 b = *(const float4*)(g_IW1 + (size_t)d * AH + part * 4);
    float h0 = a.x + b.x, h1 = a.y + b.y, h2 = a.z + b.z, h3 = a.w + b.w;
    h0 = h0 >= 0.f ? h0 : 0.2f * h0;
    h1 = h1 >= 0.f ? h1 : 0.2f * h1;
    h2 = h2 >= 0.f ? h2 : 0.2f * h2;
    h3 = h3 >= 0.f ? h3 : 0.2f * h3;
    float pz = h0 * sW2[part*4] + h1 * sW2[part*4+1] + h2 * sW2[part*4+2] + h3 * sW2[part*4+3];
    pz += __shfl_down_sync(0xFFFFFFFFu, pz, 4, 8);
    pz += __shfl_down_sync(0xFFFFFFFFu, pz, 2, 8);
    pz += __shfl_down_sync(0xFFFFFFFFu, pz, 1, 8);

    float w = -1.0f;
    if (part == 0 && valid) {
        w = 1.0f / (1.0f + expf(-(pz + b2[0])));
        g_w[e] = w;
    }
    unsigned kb = __ballot_sync(0xFFFFFFFFu, w > THRESH);
    ull p = 0ULL;
    if (part == 0 && valid)
        p = (((ull)__float_as_uint(w)) << 32) | (ull)(0xFFFFFFFFu - (unsigned)e);
    { ull q = __shfl_down_sync(0xFFFFFFFFu, p, 16); if (q > p) p = q; }
    { ull q = __shfl_down_sync(0xFFFFFFFFu, p,  8); if (q > p) p = q; }
    if (lane == 0) {
        if (kb) atomicAdd(&blkkept, __popc(kb));
        atomicMax(&blkmax, p);
    }
    __syncthreads();
    if (tid == 0) {
        if (blkkept) atomicAdd(&g_kept, blkkept);
        else         atomicMax(&g_amax, blkmax);
    }
}

__device__ __forceinline__ bool edge_kept(int e, float w) {
    if (g_kept > 0) return (w > THRESH);
    int am = (int)(0xFFFFFFFFu - (unsigned)(g_amax & 0xFFFFFFFFull));
    return (e == am);
}

// ---------------- K3: mask + denoised weights + histogram ----------------
__global__ void k_mask(const int* __restrict__ ei, float* __restrict__ wout, int E) {
    int e = blockIdx.x * blockDim.x + threadIdx.x;
    if (e >= E) return;
    float w = g_w[e];
    bool keep = edge_kept(e, w);
    wout[e] = keep ? w : 0.0f;
    if (keep) atomicAdd(&g_cnt[ei[E + e]], 1);
}

// ---------------- K4a: dinv (deg = 1 + cnt) ----------------
__global__ void k_dinv() {
    int i = blockIdx.x * blockDim.x + threadIdx.x;
    if (i < NN) g_dinv[i] = rsqrtf(1.0f + (float)g_cnt[i]);
}

// ---------------- K4b: single-block scan ----------------
#define SCHUNK 40
__global__ void k_scan() {
    __shared__ int wsum[32];
    int t = threadIdx.x;
    int lane = t & 31, wid = t >> 5;
    int base = t * SCHUNK;
    int v[SCHUNK];
    int s = 0;
    #pragma unroll
    for (int i = 0; i < SCHUNK; i++) {
        int idx = base + i;
        v[i] = (idx < NN) ? g_cnt[idx] : 0;
        s += v[i];
    }
    int incl = s;
    #pragma unroll
    for (int o = 1; o < 32; o <<= 1) {
        int u = __shfl_up_sync(0xFFFFFFFFu, incl, o);
        if (lane >= o) incl += u;
    }
    if (lane == 31) wsum[wid] = incl;
    __syncthreads();
    if (wid == 0) {
        int ws = wsum[lane];
        #pragma unroll
        for (int o = 1; o < 32; o <<= 1) {
            int u = __shfl_up_sync(0xFFFFFFFFu, ws, o);
            if (lane >= o) ws += u;
        }
        wsum[lane] = ws;
    }
    __syncthreads();
    int excl = incl - s + (wid > 0 ? wsum[wid - 1] : 0);
    #pragma unroll
    for (int i = 0; i < SCHUNK; i++) {
        int idx = base + i;
        if (idx < NN) { g_off[idx] = excl; g_cur[idx] = excl; }
        excl += v[i];
    }
}

// ---------------- K5: CSR bucket fill ----------------
__global__ void k_fill(const int* __restrict__ ei, int E) {
    int e = blockIdx.x * blockDim.x + threadIdx.x;
    if (e >= E) return;
    float w = g_w[e];
    if (!edge_kept(e, w)) return;
    int s = ei[e], d = ei[E + e];
    int p = atomicAdd(&g_cur[d], 1);
    g_srcl[p] = s;
    g_coef[p] = g_dinv[s] * g_dinv[d];
}

// ---------------- K6: HMMA bf16 3-pass GEMM, cp.async.bulk double-buffered ----
// bx0: M-block offset (grid split across two streams)
#define ASTR 40
#define STG_A_H 0
#define STG_A_L 10240
#define STG_B_H 20480
#define STG_B_L 30720
#define STG_SZ  40960
#define GSMEM   (2 * STG_SZ)   // 81920 B

__global__ void __launch_bounds__(256, 2) k_gemm_hmma(int bx0) {
    extern __shared__ char smem[];
    __shared__ ull s_mbar[2];
    uint32_t sb = s2u(smem);
    uint32_t mb0 = s2u(&s_mbar[0]), mb1 = s2u(&s_mbar[1]);
    int tid = threadIdx.x, warp = tid >> 5, lane = tid & 31;
    int bx = bx0 + blockIdx.x, by = blockIdx.y;
    int m0 = bx * 128, n0 = by * 128;
    int wm = warp >> 2, wn = warp & 3;

    int g = lane >> 3, r8 = lane & 7;
    uint32_t aoff = (uint32_t)((wm * 64 + (g & 1) * 8 + r8) * (ASTR * 2) + (g >> 1) * 16);
    uint32_t boff = (uint32_t)((wn * 32 + (g >> 1) * 8 + r8) * (ASTR * 2) + (g & 1) * 16);

    if (tid == 0) { mbar_init(mb0, 1); mbar_init(mb1, 1); }
    __syncthreads();

    float acc[4][4][4];
    #pragma unroll
    for (int i = 0; i < 4; i++)
        #pragma unroll
        for (int j = 0; j < 4; j++)
            #pragma unroll
            for (int q = 0; q < 4; q++) acc[i][j][q] = 0.f;

    auto issue_stage = [&](int c, int stg) {
        uint32_t base = sb + (uint32_t)stg * STG_SZ;
        uint32_t mb = stg ? mb1 : mb0;
        mbar_expect(mb, STG_SZ);
        bulk_ld(base + STG_A_H, g_XhiT + ((size_t)bx * 8 + c) * TB, TB, mb);
        bulk_ld(base + STG_A_L, g_XloT + ((size_t)bx * 8 + c) * TB, TB, mb);
        bulk_ld(base + STG_B_H, g_BhiT + ((size_t)by * 8 + c) * TB, TB, mb);
        bulk_ld(base + STG_B_L, g_BloT + ((size_t)by * 8 + c) * TB, TB, mb);
    };

    if (tid == 0) issue_stage(0, 0);

    #pragma unroll 1
    for (int c = 0; c < 8; c++) {
        if (c < 7 && tid == 0) issue_stage(c + 1, (c + 1) & 1);
        mbar_wait((c & 1) ? mb1 : mb0, (uint32_t)((c >> 1) & 1));

        uint32_t base = sb + (uint32_t)(c & 1) * STG_SZ;
        uint32_t sAh = base + STG_A_H + aoff, sAl = base + STG_A_L + aoff;
        uint32_t sBh = base + STG_B_H + boff, sBl = base + STG_B_L + boff;

        #pragma unroll
        for (int ks = 0; ks < 2; ks++) {
            uint32_t a[4][4], bh[2][4], bl[2][4];
            uint32_t kb = (uint32_t)(ks * 32);
            #pragma unroll
            for (int mf = 0; mf < 4; mf++) ldsm4(a[mf], sAh + mf * (16 * ASTR * 2) + kb);
            #pragma unroll
            for (int j = 0; j < 2; j++) ldsm4(bh[j], sBh + j * (16 * ASTR * 2) + kb);
            #pragma unroll
            for (int j = 0; j < 2; j++) ldsm4(bl[j], sBl + j * (16 * ASTR * 2) + kb);
            #pragma unroll
            for (int mf = 0; mf < 4; mf++)
                #pragma unroll
                for (int j = 0; j < 2; j++) {
                    mma16816(acc[mf][j*2+0], a[mf], &bh[j][0]);
                    mma16816(acc[mf][j*2+1], a[mf], &bh[j][2]);
                    mma16816(acc[mf][j*2+0], a[mf], &bl[j][0]);
                    mma16816(acc[mf][j*2+1], a[mf], &bl[j][2]);
                }
            #pragma unroll
            for (int mf = 0; mf < 4; mf++) ldsm4(a[mf], sAl + mf * (16 * ASTR * 2) + kb);
            #pragma unroll
            for (int mf = 0; mf < 4; mf++)
                #pragma unroll
                for (int j = 0; j < 2; j++) {
                    mma16816(acc[mf][j*2+0], a[mf], &bh[j][0]);
                    mma16816(acc[mf][j*2+1], a[mf], &bh[j][2]);
                }
        }
        __syncthreads();   // all warps done with this buffer before it is re-issued
    }

    int qr = lane >> 2, qc = (lane & 3) * 2;
    #pragma unroll
    for (int mf = 0; mf < 4; mf++) {
        int mrow = m0 + wm * 64 + mf * 16 + qr;
        #pragma unroll
        for (int nf = 0; nf < 4; nf++) {
            int col = n0 + wn * 32 + nf * 8 + qc;
            if (mrow < NN)
                *(float2*)&g_xw[(size_t)mrow * HID + col] = make_float2(acc[mf][nf][0], acc[mf][nf][1]);
            if (mrow + 8 < NN)
                *(float2*)&g_xw[(size_t)(mrow + 8) * HID + col] = make_float2(acc[mf][nf][2], acc[mf][nf][3]);
        }
    }
}

// ---------------- K7: per-node aggregate + self-loop + bias ----------------
__global__ void k_agg(const float* __restrict__ bias, float* __restrict__ out) {
    int n = blockIdx.x, t = threadIdx.x;
    __shared__ int   ss[64];
    __shared__ float sc[64];
    float di = g_dinv[n];
    float acc = g_xw[(size_t)n * HID + t] * (di * di) + bias[t];
    int beg = g_off[n], cnt = g_cnt[n];
    for (int base = 0; base < cnt; base += 64) {
        int nb = min(64, cnt - base);
        if (t < nb) {
            ss[t] = g_srcl[beg + base + t];
            sc[t] = g_coef[beg + base + t];
        }
        __syncthreads();
        for (int j = 0; j < nb; j++)
            acc += sc[j] * g_xw[(size_t)ss[j] * HID + t];
        __syncthreads();
    }
    out[(size_t)n * HID + t] = acc;
}

// ---------------- launch: fork/join + GEMM split across both streams ---------
extern "C" void kernel_launch(void* const* d_in, const int* in_sizes, int n_in,
                              void* d_out, int out_size) {
    const float* U  = (const float*)d_in[0];
    const float* I  = (const float*)d_in[1];
    const int*   ei = (const int*)  d_in[2];
    const float* W1 = (const float*)d_in[3];
    const float* b1 = (const float*)d_in[4];
    const float* W2 = (const float*)d_in[5];
    const float* b2 = (const float*)d_in[6];
    const float* GW = (const float*)d_in[7];
    const float* Gb = (const float*)d_in[8];
    int E = in_sizes[2] / 2;

    float* out  = (float*)d_out;
    float* wout = out + (size_t)NN * HID;

    static cudaStream_t s2 = nullptr;
    static cudaEvent_t evFork = nullptr, evPrep = nullptr, evJoin = nullptr;
    if (!s2) {
        cudaStreamCreateWithFlags(&s2, cudaStreamNonBlocking);
        cudaEventCreateWithFlags(&evFork, cudaEventDisableTiming);
        cudaEventCreateWithFlags(&evPrep, cudaEventDisableTiming);
        cudaEventCreateWithFlags(&evJoin, cudaEventDisableTiming);
        cudaFuncSetAttribute(k_gemm_hmma, cudaFuncAttributeMaxDynamicSharedMemorySize, GSMEM);
    }

    // fork: side stream preps operands, then runs the LARGE GEMM piece
    cudaEventRecord(evFork, 0);
    cudaStreamWaitEvent(s2, evFork, 0);
    k_prepW<<<HID * HID / 256, 256, 0, s2>>>(GW);
    k_prepX<<<(int)(((size_t)NN * HID / 4) / 256), 256, 0, s2>>>(U, I);
    cudaEventRecord(evPrep, s2);
    k_gemm_hmma<<<dim3(MBLKS - SPLIT_MAIN, HID / 128), 256, GSMEM, s2>>>(SPLIT_MAIN);
    cudaEventRecord(evJoin, s2);

    // main stream: init -> proj -> edge -> mask -> dinv -> scan -> fill
    k_init<<<(NN + 255) / 256, 256>>>();
    k_projB<<<UB2 + IB2, 256>>>(U, I, W1, b1);
    k_edge<<<((E + 3) / 4 * 32 + 255) / 256, 256>>>(ei, W2, b2, E);
    k_mask<<<(E + 255) / 256, 256>>>(ei, wout, E);
    k_dinv<<<(NN + 255) / 256, 256>>>();
    k_scan<<<1, 1024>>>();
    k_fill<<<(E + 255) / 256, 256>>>(ei, E);

    // main stream runs the SMALL GEMM piece (needs prepX/prepW done on s2)
    cudaStreamWaitEvent(0, evPrep, 0);
    k_gemm_hmma<<<dim3(SPLIT_MAIN, HID / 128), 256, GSMEM, 0>>>(0);

    // join: aggregate needs all of g_xw and the CSR
    cudaStreamWaitEvent(0, evJoin, 0);
    k_agg<<<NN, 256>>>(Gb, out);
}

// round 15
// speedup vs baseline: 1.1441x; 1.1441x over previous
#include <cuda_runtime.h>
#include <cuda_bf16.h>
#include <cuda_fp16.h>
#include <cstdint>

#define HID 256
#define AH  32
#define NU  10000
#define NI  30000
#define NN  40000
#define NE  500000
#define THRESH 0.8f

#define MBLKS 313            // ceil(NN/128)
#define TB    10240          // one tile: 128 rows x 80 B

typedef unsigned long long ull;

// ---------------- device scratch ----------------
__device__ float g_UW1[NU * AH];
__device__ float g_IW1[NI * AH];
__device__ float g_w[NE];
__device__ float g_xw[(size_t)NN * HID];
__device__ float g_dinv[NN];
__device__ int   g_cnt[NN];
__device__ int   g_off[NN];
__device__ int   g_cur[NN];
__device__ int   g_srcl[NE];
__device__ float g_coef[NE];
__device__ ull   g_amax;
__device__ int   g_kept;
// tile-blocked fp16 operands: [blk][kchunk(8)][128 rows][80 B]
__device__ __align__(128) unsigned char g_XT[(size_t)MBLKS * 8 * TB];
__device__ __align__(128) unsigned char g_BT[2 * 8 * TB];

// ---------------- helpers ----------------
__device__ __forceinline__ uint32_t s2u(const void* p) {
    uint32_t a;
    asm("{ .reg .u64 t; cvta.to.shared.u64 t, %1; cvt.u32.u64 %0, t; }" : "=r"(a) : "l"(p));
    return a;
}
__device__ __forceinline__ void ldsm4(uint32_t* r, uint32_t addr) {
    asm volatile("ldmatrix.sync.aligned.m8n8.x4.shared.b16 {%0,%1,%2,%3}, [%4];"
                 : "=r"(r[0]), "=r"(r[1]), "=r"(r[2]), "=r"(r[3]) : "r"(addr));
}
__device__ __forceinline__ void mma16816h(float* c, const uint32_t* a, const uint32_t* b) {
    asm volatile("mma.sync.aligned.m16n8k16.row.col.f32.f16.f16.f32 "
                 "{%0,%1,%2,%3}, {%4,%5,%6,%7}, {%8,%9}, {%0,%1,%2,%3};"
                 : "+f"(c[0]), "+f"(c[1]), "+f"(c[2]), "+f"(c[3])
                 : "r"(a[0]), "r"(a[1]), "r"(a[2]), "r"(a[3]), "r"(b[0]), "r"(b[1]));
}
__device__ __forceinline__ ull pk2(float x, float y) {
    ull r; asm("mov.b64 %0, {%1, %2};" : "=l"(r) : "f"(x), "f"(y)); return r;
}
__device__ __forceinline__ void ffma2(ull& d, ull a, ull b) {
    asm("fma.rn.f32x2 %0, %1, %2, %0;" : "+l"(d) : "l"(a), "l"(b));
}
__device__ __forceinline__ void bulk_ld(uint32_t dst, const void* src, uint32_t bytes, uint32_t mbar) {
    asm volatile("cp.async.bulk.shared::cluster.global.mbarrier::complete_tx::bytes "
                 "[%0], [%1], %2, [%3];"
                 :: "r"(dst), "l"(src), "r"(bytes), "r"(mbar) : "memory");
}
__device__ __forceinline__ void mbar_init(uint32_t a, uint32_t cnt) {
    asm volatile("mbarrier.init.shared.b64 [%0], %1;" :: "r"(a), "r"(cnt) : "memory");
}
__device__ __forceinline__ void mbar_expect(uint32_t a, uint32_t bytes) {
    asm volatile("mbarrier.arrive.expect_tx.shared.b64 _, [%0], %1;" :: "r"(a), "r"(bytes) : "memory");
}
__device__ __forceinline__ void mbar_wait(uint32_t a, uint32_t par) {
    asm volatile(
        "{ .reg .pred P;\n"
        "W%=: mbarrier.try_wait.parity.acquire.cta.shared::cta.b64 P, [%0], %1, 0x989680;\n"
        "@P bra D%=; bra W%=; D%=: }"
        :: "r"(a), "r"(par) : "memory");
}

// ---------------- K0: reset ----------------
__global__ void k_init() {
    int i = blockIdx.x * blockDim.x + threadIdx.x;
    if (i < NN) g_cnt[i] = 0;
    if (i == 0) { g_amax = 0ULL; g_kept = 0; }
}

// ---------------- prepW: transpose + fp16 cast into tiled layout --------------
__global__ void k_prepW(const float* __restrict__ W) {
    int i = blockIdx.x * blockDim.x + threadIdx.x;   // 65536
    int n = i & 255, k = i >> 8;
    float v = W[k * HID + n];
    int nblk = n >> 7, r = n & 127, kc = k >> 5, col = k & 31;
    size_t off = ((size_t)(nblk * 8 + kc) * 128 + r) * 80 + col * 2;
    *(__half*)(g_BT + off) = __float2half_rn(v);
}

// ---------------- prepX: fp16 cast of concat(U,I) into tiled layout -----------
__global__ void k_prepX(const float* __restrict__ U, const float* __restrict__ I) {
    size_t i = ((size_t)blockIdx.x * 256 + threadIdx.x) * 4;   // grid 10000 exact
    int m = (int)(i >> 8), k = (int)(i & 255);
    const float* x = (m < NU) ? U + (size_t)m * HID : I + (size_t)(m - NU) * HID;
    float4 v = *(const float4*)(x + k);
    __half2 p0 = __floats2half2_rn(v.x, v.y);
    __half2 p1 = __floats2half2_rn(v.z, v.w);
    int mblk = m >> 7, r = m & 127, kc = k >> 5, col = k & 31;
    size_t off = ((size_t)(mblk * 8 + kc) * 128 + r) * 80 + col * 2;
    *(uint2*)(g_XT + off) = make_uint2(*(uint32_t*)&p0, *(uint32_t*)&p1);
}

// ---------------- K1: merged node projection, f32x2 packed, 64-row tiles -----
#define UB2 ((NU + 63) / 64)   // 157
#define IB2 ((NI + 63) / 64)   // 469
__global__ void k_projB(const float* __restrict__ U, const float* __restrict__ I,
                        const float* __restrict__ W1, const float* __restrict__ b1) {
    __shared__ float Xs[32][66];
    __shared__ float Ws[32][32];
    const float* X; const float* Wp; const float* bv; float* P;
    int nrows, m0;
    if (blockIdx.x < UB2) {
        X = U;  Wp = W1;            bv = b1;      P = g_UW1; nrows = NU;
        m0 = blockIdx.x * 64;
    } else {
        X = I;  Wp = W1 + HID * AH; bv = nullptr; P = g_IW1; nrows = NI;
        m0 = (blockIdx.x - UB2) * 64;
    }
    int tid = threadIdx.x;
    int tr = tid >> 4, tc = tid & 15;
    ull acc[2][2] = {};
    for (int kc = 0; kc < HID; kc += 32) {
        if (kc) __syncthreads();
        for (int i = tid; i < 512; i += 256) {
            int r = i >> 3, q = i & 7;
            int m = m0 + r; if (m >= nrows) m = nrows - 1;
            float4 v = *(const float4*)(X + (size_t)m * HID + kc + q * 4);
            Xs[q*4+0][r] = v.x; Xs[q*4+1][r] = v.y;
            Xs[q*4+2][r] = v.z; Xs[q*4+3][r] = v.w;
        }
        {
            int r = tid >> 3, q = tid & 7;
            *(float4*)&Ws[r][q * 4] = *(const float4*)(Wp + (size_t)(kc + r) * AH + q * 4);
        }
        __syncthreads();
        #pragma unroll
        for (int k = 0; k < 32; k++) {
            ull a0 = *(const ull*)&Xs[k][tr * 4 + 0];
            ull a1 = *(const ull*)&Xs[k][tr * 4 + 2];
            float2 bw = *(const float2*)&Ws[k][tc * 2];
            ull b0 = pk2(bw.x, bw.x), b1v = pk2(bw.y, bw.y);
            ffma2(acc[0][0], a0, b0); ffma2(acc[0][1], a0, b1v);
            ffma2(acc[1][0], a1, b0); ffma2(acc[1][1], a1, b1v);
        }
    }
    float bb0 = bv ? bv[tc * 2] : 0.f, bb1 = bv ? bv[tc * 2 + 1] : 0.f;
    #pragma unroll
    for (int p = 0; p < 2; p++) {
        float2 c0 = *(float2*)&acc[p][0];
        float2 c1 = *(float2*)&acc[p][1];
        int r0 = m0 + tr * 4 + 2 * p;
        if (r0 < nrows)
            *(float2*)&P[(size_t)r0 * AH + tc * 2] = make_float2(c0.x + bb0, c1.x + bb1);
        if (r0 + 1 < nrows)
            *(float2*)&P[(size_t)(r0 + 1) * AH + tc * 2] = make_float2(c0.y + bb0, c1.y + bb1);
    }
}

// ---------------- K2: edge attention (8 lanes per edge) ----------------
__global__ void k_edge(const int* __restrict__ ei, const float* __restrict__ W2,
                       const float* __restrict__ b2, int E) {
    __shared__ float sW2[AH];
    __shared__ ull   blkmax;
    __shared__ int   blkkept;
    int tid = threadIdx.x;
    if (tid < AH) sW2[tid] = W2[tid];
    if (tid == 0) { blkmax = 0ULL; blkkept = 0; }
    __syncthreads();

    int lane = tid & 31;
    int gw = (blockIdx.x * blockDim.x + tid) >> 5;
    int sub = lane >> 3, part = lane & 7;
    int e = gw * 4 + sub;
    bool valid = e < E;
    int s = 0, d = 0;
    if (valid) { s = ei[e]; d = ei[E + e]; }

    float4 a = *(const float4*)(g_UW1 + (size_t)s * AH + part * 4);
    float4 b = *(const float4*)(g_IW1 + (size_t)d * AH + part * 4);
    float h0 = a.x + b.x, h1 = a.y + b.y, h2 = a.z + b.z, h3 = a.w + b.w;
    h0 = h0 >= 0.f ? h0 : 0.2f * h0;
    h1 = h1 >= 0.f ? h1 : 0.2f * h1;
    h2 = h2 >= 0.f ? h2 : 0.2f * h2;
    h3 = h3 >= 0.f ? h3 : 0.2f * h3;
    float pz = h0 * sW2[part*4] + h1 * sW2[part*4+1] + h2 * sW2[part*4+2] + h3 * sW2[part*4+3];
    pz += __shfl_down_sync(0xFFFFFFFFu, pz, 4, 8);
    pz += __shfl_down_sync(0xFFFFFFFFu, pz, 2, 8);
    pz += __shfl_down_sync(0xFFFFFFFFu, pz, 1, 8);

    float w = -1.0f;
    if (part == 0 && valid) {
        w = 1.0f / (1.0f + expf(-(pz + b2[0])));
        g_w[e] = w;
    }
    unsigned kb = __ballot_sync(0xFFFFFFFFu, w > THRESH);
    ull p = 0ULL;
    if (part == 0 && valid)
        p = (((ull)__float_as_uint(w)) << 32) | (ull)(0xFFFFFFFFu - (unsigned)e);
    { ull q = __shfl_down_sync(0xFFFFFFFFu, p, 16); if (q > p) p = q; }
    { ull q = __shfl_down_sync(0xFFFFFFFFu, p,  8); if (q > p) p = q; }
    if (lane == 0) {
        if (kb) atomicAdd(&blkkept, __popc(kb));
        atomicMax(&blkmax, p);
    }
    __syncthreads();
    if (tid == 0) {
        if (blkkept) atomicAdd(&g_kept, blkkept);
        else         atomicMax(&g_amax, blkmax);
    }
}

__device__ __forceinline__ bool edge_kept(int e, float w) {
    if (g_kept > 0) return (w > THRESH);
    int am = (int)(0xFFFFFFFFu - (unsigned)(g_amax & 0xFFFFFFFFull));
    return (e == am);
}

// ---------------- K3: mask + denoised weights + histogram ----------------
__global__ void k_mask(const int* __restrict__ ei, float* __restrict__ wout, int E) {
    int e = blockIdx.x * blockDim.x + threadIdx.x;
    if (e >= E) return;
    float w = g_w[e];
    bool keep = edge_kept(e, w);
    wout[e] = keep ? w : 0.0f;
    if (keep) atomicAdd(&g_cnt[ei[E + e]], 1);
}

// ---------------- K4a: dinv (deg = 1 + cnt) ----------------
__global__ void k_dinv() {
    int i = blockIdx.x * blockDim.x + threadIdx.x;
    if (i < NN) g_dinv[i] = rsqrtf(1.0f + (float)g_cnt[i]);
}

// ---------------- K4b: single-block scan ----------------
#define SCHUNK 40
__global__ void k_scan() {
    __shared__ int wsum[32];
    int t = threadIdx.x;
    int lane = t & 31, wid = t >> 5;
    int base = t * SCHUNK;
    int v[SCHUNK];
    int s = 0;
    #pragma unroll
    for (int i = 0; i < SCHUNK; i++) {
        int idx = base + i;
        v[i] = (idx < NN) ? g_cnt[idx] : 0;
        s += v[i];
    }
    int incl = s;
    #pragma unroll
    for (int o = 1; o < 32; o <<= 1) {
        int u = __shfl_up_sync(0xFFFFFFFFu, incl, o);
        if (lane >= o) incl += u;
    }
    if (lane == 31) wsum[wid] = incl;
    __syncthreads();
    if (wid == 0) {
        int ws = wsum[lane];
        #pragma unroll
        for (int o = 1; o < 32; o <<= 1) {
            int u = __shfl_up_sync(0xFFFFFFFFu, ws, o);
            if (lane >= o) ws += u;
        }
        wsum[lane] = ws;
    }
    __syncthreads();
    int excl = incl - s + (wid > 0 ? wsum[wid - 1] : 0);
    #pragma unroll
    for (int i = 0; i < SCHUNK; i++) {
        int idx = base + i;
        if (idx < NN) { g_off[idx] = excl; g_cur[idx] = excl; }
        excl += v[i];
    }
}

// ---------------- K5: CSR bucket fill ----------------
__global__ void k_fill(const int* __restrict__ ei, int E) {
    int e = blockIdx.x * blockDim.x + threadIdx.x;
    if (e >= E) return;
    float w = g_w[e];
    if (!edge_kept(e, w)) return;
    int s = ei[e], d = ei[E + e];
    int p = atomicAdd(&g_cur[d], 1);
    g_srcl[p] = s;
    g_coef[p] = g_dinv[s] * g_dinv[d];
}

// ---------------- K6: HMMA fp16 single-pass GEMM, bulk double-buffered --------
#define ASTR 40
#define STG_A 0
#define STG_B 10240
#define STG_SZ 20480
#define GSMEM (2 * STG_SZ)   // 40960 B

__global__ void __launch_bounds__(256, 2) k_gemm_hmma() {
    extern __shared__ char smem[];
    __shared__ ull s_mbar[2];
    uint32_t sb = s2u(smem);
    uint32_t mb0 = s2u(&s_mbar[0]), mb1 = s2u(&s_mbar[1]);
    int tid = threadIdx.x, warp = tid >> 5, lane = tid & 31;
    int bx = blockIdx.x, by = blockIdx.y;
    int m0 = bx * 128, n0 = by * 128;
    int wm = warp >> 2, wn = warp & 3;

    int g = lane >> 3, r8 = lane & 7;
    uint32_t aoff = (uint32_t)((wm * 64 + (g & 1) * 8 + r8) * (ASTR * 2) + (g >> 1) * 16);
    uint32_t boff = (uint32_t)((wn * 32 + (g >> 1) * 8 + r8) * (ASTR * 2) + (g & 1) * 16);

    if (tid == 0) { mbar_init(mb0, 1); mbar_init(mb1, 1); }
    __syncthreads();

    float acc[4][4][4];
    #pragma unroll
    for (int i = 0; i < 4; i++)
        #pragma unroll
        for (int j = 0; j < 4; j++)
            #pragma unroll
            for (int q = 0; q < 4; q++) acc[i][j][q] = 0.f;

    auto issue_stage = [&](int c, int stg) {
        uint32_t base = sb + (uint32_t)stg * STG_SZ;
        uint32_t mb = stg ? mb1 : mb0;
        mbar_expect(mb, STG_SZ);
        bulk_ld(base + STG_A, g_XT + ((size_t)bx * 8 + c) * TB, TB, mb);
        bulk_ld(base + STG_B, g_BT + ((size_t)by * 8 + c) * TB, TB, mb);
    };

    if (tid == 0) issue_stage(0, 0);

    #pragma unroll 1
    for (int c = 0; c < 8; c++) {
        if (c < 7 && tid == 0) issue_stage(c + 1, (c + 1) & 1);
        mbar_wait((c & 1) ? mb1 : mb0, (uint32_t)((c >> 1) & 1));

        uint32_t base = sb + (uint32_t)(c & 1) * STG_SZ;
        uint32_t sA = base + STG_A + aoff, sB = base + STG_B + boff;

        #pragma unroll
        for (int ks = 0; ks < 2; ks++) {
            uint32_t a[4][4], b[2][4];
            uint32_t kb = (uint32_t)(ks * 32);
            #pragma unroll
            for (int mf = 0; mf < 4; mf++) ldsm4(a[mf], sA + mf * (16 * ASTR * 2) + kb);
            #pragma unroll
            for (int j = 0; j < 2; j++) ldsm4(b[j], sB + j * (16 * ASTR * 2) + kb);
            #pragma unroll
            for (int mf = 0; mf < 4; mf++)
                #pragma unroll
                for (int j = 0; j < 2; j++) {
                    mma16816h(acc[mf][j*2+0], a[mf], &b[j][0]);
                    mma16816h(acc[mf][j*2+1], a[mf], &b[j][2]);
                }
        }
        __syncthreads();   // all warps done with this buffer before re-issue
    }

    int qr = lane >> 2, qc = (lane & 3) * 2;
    #pragma unroll
    for (int mf = 0; mf < 4; mf++) {
        int mrow = m0 + wm * 64 + mf * 16 + qr;
        #pragma unroll
        for (int nf = 0; nf < 4; nf++) {
            int col = n0 + wn * 32 + nf * 8 + qc;
            if (mrow < NN)
                *(float2*)&g_xw[(size_t)mrow * HID + col] = make_float2(acc[mf][nf][0], acc[mf][nf][1]);
            if (mrow + 8 < NN)
                *(float2*)&g_xw[(size_t)(mrow + 8) * HID + col] = make_float2(acc[mf][nf][2], acc[mf][nf][3]);
        }
    }
}

// ---------------- K7: per-node aggregate + self-loop + bias ----------------
__global__ void k_agg(const float* __restrict__ bias, float* __restrict__ out) {
    int n = blockIdx.x, t = threadIdx.x;
    __shared__ int   ss[64];
    __shared__ float sc[64];
    float di = g_dinv[n];
    float acc = g_xw[(size_t)n * HID + t] * (di * di) + bias[t];
    int beg = g_off[n], cnt = g_cnt[n];
    for (int base = 0; base < cnt; base += 64) {
        int nb = min(64, cnt - base);
        if (t < nb) {
            ss[t] = g_srcl[beg + base + t];
            sc[t] = g_coef[beg + base + t];
        }
        __syncthreads();
        for (int j = 0; j < nb; j++)
            acc += sc[j] * g_xw[(size_t)ss[j] * HID + t];
        __syncthreads();
    }
    out[(size_t)n * HID + t] = acc;
}

// ---------------- launch: fork/join overlap (round-13 structure) -------------
extern "C" void kernel_launch(void* const* d_in, const int* in_sizes, int n_in,
                              void* d_out, int out_size) {
    const float* U  = (const float*)d_in[0];
    const float* I  = (const float*)d_in[1];
    const int*   ei = (const int*)  d_in[2];
    const float* W1 = (const float*)d_in[3];
    const float* b1 = (const float*)d_in[4];
    const float* W2 = (const float*)d_in[5];
    const float* b2 = (const float*)d_in[6];
    const float* GW = (const float*)d_in[7];
    const float* Gb = (const float*)d_in[8];
    int E = in_sizes[2] / 2;

    float* out  = (float*)d_out;
    float* wout = out + (size_t)NN * HID;

    static cudaStream_t s2 = nullptr;
    static cudaEvent_t evFork = nullptr, evJoin = nullptr;
    if (!s2) {
        cudaStreamCreateWithFlags(&s2, cudaStreamNonBlocking);
        cudaEventCreateWithFlags(&evFork, cudaEventDisableTiming);
        cudaEventCreateWithFlags(&evJoin, cudaEventDisableTiming);
        cudaFuncSetAttribute(k_gemm_hmma, cudaFuncAttributeMaxDynamicSharedMemorySize, GSMEM);
    }

    // fork: side stream runs the GEMM chain
    cudaEventRecord(evFork, 0);
    cudaStreamWaitEvent(s2, evFork, 0);
    k_prepW<<<HID * HID / 256, 256, 0, s2>>>(GW);
    k_prepX<<<(int)(((size_t)NN * HID / 4) / 256), 256, 0, s2>>>(U, I);
    k_gemm_hmma<<<dim3(MBLKS, HID / 128), 256, GSMEM, s2>>>();
    cudaEventRecord(evJoin, s2);

    // main stream: init -> proj -> edge -> mask -> dinv -> scan -> fill
    k_init<<<(NN + 255) / 256, 256>>>();
    k_projB<<<UB2 + IB2, 256>>>(U, I, W1, b1);
    k_edge<<<((E + 3) / 4 * 32 + 255) / 256, 256>>>(ei, W2, b2, E);
    k_mask<<<(E + 255) / 256, 256>>>(ei, wout, E);
    k_dinv<<<(NN + 255) / 256, 256>>>();
    k_scan<<<1, 1024>>>();
    k_fill<<<(E + 255) / 256, 256>>>(ei, E);

    // join: aggregate needs both g_xw and the CSR
    cudaStreamWaitEvent(0, evJoin, 0);
    k_agg<<<NN, 256>>>(Gb, out);
}

// round 16
// speedup vs baseline: 1.1461x; 1.0017x over previous
#include <cuda_runtime.h>
#include <cuda_bf16.h>
#include <cuda_fp16.h>
#include <cstdint>

#define HID 256
#define AH  32
#define NU  10000
#define NI  30000
#define NN  40000
#define NE  500000
#define THRESH 0.8f

#define MBLKS 313            // ceil(NN/128)
#define TB    10240          // one tile: 128 rows x 80 B

typedef unsigned long long ull;

// ---------------- device scratch ----------------
__device__ float g_UW1[NU * AH];
__device__ float g_IW1[NI * AH];
__device__ float g_w[NE];
__device__ float g_xw[(size_t)NN * HID];
__device__ float g_dinv[NN];
__device__ int   g_cnt[NN];
__device__ int   g_off[NN];
__device__ int   g_cur[NN];
__device__ int   g_srcl[NE];
__device__ float g_coef[NE];
__device__ ull   g_amax;
__device__ int   g_kept;
// tile-blocked fp16 operands: [blk][kchunk(8)][128 rows][80 B]
__device__ __align__(128) unsigned char g_XT[(size_t)MBLKS * 8 * TB];
__device__ __align__(128) unsigned char g_BT[2 * 8 * TB];

// ---------------- helpers ----------------
__device__ __forceinline__ uint32_t s2u(const void* p) {
    uint32_t a;
    asm("{ .reg .u64 t; cvta.to.shared.u64 t, %1; cvt.u32.u64 %0, t; }" : "=r"(a) : "l"(p));
    return a;
}
__device__ __forceinline__ void ldsm4(uint32_t* r, uint32_t addr) {
    asm volatile("ldmatrix.sync.aligned.m8n8.x4.shared.b16 {%0,%1,%2,%3}, [%4];"
                 : "=r"(r[0]), "=r"(r[1]), "=r"(r[2]), "=r"(r[3]) : "r"(addr));
}
__device__ __forceinline__ void mma16816h(float* c, const uint32_t* a, const uint32_t* b) {
    asm volatile("mma.sync.aligned.m16n8k16.row.col.f32.f16.f16.f32 "
                 "{%0,%1,%2,%3}, {%4,%5,%6,%7}, {%8,%9}, {%0,%1,%2,%3};"
                 : "+f"(c[0]), "+f"(c[1]), "+f"(c[2]), "+f"(c[3])
                 : "r"(a[0]), "r"(a[1]), "r"(a[2]), "r"(a[3]), "r"(b[0]), "r"(b[1]));
}
__device__ __forceinline__ ull pk2(float x, float y) {
    ull r; asm("mov.b64 %0, {%1, %2};" : "=l"(r) : "f"(x), "f"(y)); return r;
}
__device__ __forceinline__ void ffma2(ull& d, ull a, ull b) {
    asm("fma.rn.f32x2 %0, %1, %2, %0;" : "+l"(d) : "l"(a), "l"(b));
}
__device__ __forceinline__ void bulk_ld(uint32_t dst, const void* src, uint32_t bytes, uint32_t mbar) {
    asm volatile("cp.async.bulk.shared::cluster.global.mbarrier::complete_tx::bytes "
                 "[%0], [%1], %2, [%3];"
                 :: "r"(dst), "l"(src), "r"(bytes), "r"(mbar) : "memory");
}
__device__ __forceinline__ void mbar_init(uint32_t a, uint32_t cnt) {
    asm volatile("mbarrier.init.shared.b64 [%0], %1;" :: "r"(a), "r"(cnt) : "memory");
}
__device__ __forceinline__ void mbar_expect(uint32_t a, uint32_t bytes) {
    asm volatile("mbarrier.arrive.expect_tx.shared.b64 _, [%0], %1;" :: "r"(a), "r"(bytes) : "memory");
}
__device__ __forceinline__ void mbar_wait(uint32_t a, uint32_t par) {
    asm volatile(
        "{ .reg .pred P;\n"
        "W%=: mbarrier.try_wait.parity.acquire.cta.shared::cta.b64 P, [%0], %1, 0x989680;\n"
        "@P bra D%=; bra W%=; D%=: }"
        :: "r"(a), "r"(par) : "memory");
}

// ---------------- K0: reset ----------------
__global__ void k_init() {
    int i = blockIdx.x * blockDim.x + threadIdx.x;
    if (i < NN) g_cnt[i] = 0;
    if (i == 0) { g_amax = 0ULL; g_kept = 0; }
}

// ---------------- prepW: transpose + fp16 cast into tiled layout --------------
__global__ void k_prepW(const float* __restrict__ W) {
    int i = blockIdx.x * blockDim.x + threadIdx.x;   // 65536
    int n = i & 255, k = i >> 8;
    float v = W[k * HID + n];
    int nblk = n >> 7, r = n & 127, kc = k >> 5, col = k & 31;
    size_t off = ((size_t)(nblk * 8 + kc) * 128 + r) * 80 + col * 2;
    *(__half*)(g_BT + off) = __float2half_rn(v);
}

// ---------------- prepX: fp16 cast of concat(U,I) into tiled layout -----------
__global__ void k_prepX(const float* __restrict__ U, const float* __restrict__ I) {
    size_t i = ((size_t)blockIdx.x * 256 + threadIdx.x) * 4;   // grid 10000 exact
    int m = (int)(i >> 8), k = (int)(i & 255);
    const float* x = (m < NU) ? U + (size_t)m * HID : I + (size_t)(m - NU) * HID;
    float4 v = *(const float4*)(x + k);
    __half2 p0 = __floats2half2_rn(v.x, v.y);
    __half2 p1 = __floats2half2_rn(v.z, v.w);
    int mblk = m >> 7, r = m & 127, kc = k >> 5, col = k & 31;
    size_t off = ((size_t)(mblk * 8 + kc) * 128 + r) * 80 + col * 2;
    *(uint2*)(g_XT + off) = make_uint2(*(uint32_t*)&p0, *(uint32_t*)&p1);
}

// ---------------- K1: merged node projection, f32x2 packed, 64-row tiles -----
#define UB2 ((NU + 63) / 64)   // 157
#define IB2 ((NI + 63) / 64)   // 469
__global__ void k_projB(const float* __restrict__ U, const float* __restrict__ I,
                        const float* __restrict__ W1, const float* __restrict__ b1) {
    __shared__ float Xs[32][66];
    __shared__ float Ws[32][32];
    const float* X; const float* Wp; const float* bv; float* P;
    int nrows, m0;
    if (blockIdx.x < UB2) {
        X = U;  Wp = W1;            bv = b1;      P = g_UW1; nrows = NU;
        m0 = blockIdx.x * 64;
    } else {
        X = I;  Wp = W1 + HID * AH; bv = nullptr; P = g_IW1; nrows = NI;
        m0 = (blockIdx.x - UB2) * 64;
    }
    int tid = threadIdx.x;
    int tr = tid >> 4, tc = tid & 15;
    ull acc[2][2] = {};
    for (int kc = 0; kc < HID; kc += 32) {
        if (kc) __syncthreads();
        for (int i = tid; i < 512; i += 256) {
            int r = i >> 3, q = i & 7;
            int m = m0 + r; if (m >= nrows) m = nrows - 1;
            float4 v = *(const float4*)(X + (size_t)m * HID + kc + q * 4);
            Xs[q*4+0][r] = v.x; Xs[q*4+1][r] = v.y;
            Xs[q*4+2][r] = v.z; Xs[q*4+3][r] = v.w;
        }
        {
            int r = tid >> 3, q = tid & 7;
            *(float4*)&Ws[r][q * 4] = *(const float4*)(Wp + (size_t)(kc + r) * AH + q * 4);
        }
        __syncthreads();
        #pragma unroll
        for (int k = 0; k < 32; k++) {
            ull a0 = *(const ull*)&Xs[k][tr * 4 + 0];
            ull a1 = *(const ull*)&Xs[k][tr * 4 + 2];
            float2 bw = *(const float2*)&Ws[k][tc * 2];
            ull b0 = pk2(bw.x, bw.x), b1v = pk2(bw.y, bw.y);
            ffma2(acc[0][0], a0, b0); ffma2(acc[0][1], a0, b1v);
            ffma2(acc[1][0], a1, b0); ffma2(acc[1][1], a1, b1v);
        }
    }
    float bb0 = bv ? bv[tc * 2] : 0.f, bb1 = bv ? bv[tc * 2 + 1] : 0.f;
    #pragma unroll
    for (int p = 0; p < 2; p++) {
        float2 c0 = *(float2*)&acc[p][0];
        float2 c1 = *(float2*)&acc[p][1];
        int r0 = m0 + tr * 4 + 2 * p;
        if (r0 < nrows)
            *(float2*)&P[(size_t)r0 * AH + tc * 2] = make_float2(c0.x + bb0, c1.x + bb1);
        if (r0 + 1 < nrows)
            *(float2*)&P[(size_t)(r0 + 1) * AH + tc * 2] = make_float2(c0.y + bb0, c1.y + bb1);
    }
}

// ---------------- K2: edge attention (8 lanes per edge) ----------------
__global__ void k_edge(const int* __restrict__ ei, const float* __restrict__ W2,
                       const float* __restrict__ b2, int E) {
    __shared__ float sW2[AH];
    __shared__ ull   blkmax;
    __shared__ int   blkkept;
    int tid = threadIdx.x;
    if (tid < AH) sW2[tid] = W2[tid];
    if (tid == 0) { blkmax = 0ULL; blkkept = 0; }
    __syncthreads();

    int lane = tid & 31;
    int gw = (blockIdx.x * blockDim.x + tid) >> 5;
    int sub = lane >> 3, part = lane & 7;
    int e = gw * 4 + sub;
    bool valid = e < E;
    int s = 0, d = 0;
    if (valid) { s = ei[e]; d = ei[E + e]; }

    float4 a = *(const float4*)(g_UW1 + (size_t)s * AH + part * 4);
    float4 b = *(const float4*)(g_IW1 + (size_t)d * AH + part * 4);
    float h0 = a.x + b.x, h1 = a.y + b.y, h2 = a.z + b.z, h3 = a.w + b.w;
    h0 = h0 >= 0.f ? h0 : 0.2f * h0;
    h1 = h1 >= 0.f ? h1 : 0.2f * h1;
    h2 = h2 >= 0.f ? h2 : 0.2f * h2;
    h3 = h3 >= 0.f ? h3 : 0.2f * h3;
    float pz = h0 * sW2[part*4] + h1 * sW2[part*4+1] + h2 * sW2[part*4+2] + h3 * sW2[part*4+3];
    pz += __shfl_down_sync(0xFFFFFFFFu, pz, 4, 8);
    pz += __shfl_down_sync(0xFFFFFFFFu, pz, 2, 8);
    pz += __shfl_down_sync(0xFFFFFFFFu, pz, 1, 8);

    float w = -1.0f;
    if (part == 0 && valid) {
        w = 1.0f / (1.0f + expf(-(pz + b2[0])));
        g_w[e] = w;
    }
    unsigned kb = __ballot_sync(0xFFFFFFFFu, w > THRESH);
    ull p = 0ULL;
    if (part == 0 && valid)
        p = (((ull)__float_as_uint(w)) << 32) | (ull)(0xFFFFFFFFu - (unsigned)e);
    { ull q = __shfl_down_sync(0xFFFFFFFFu, p, 16); if (q > p) p = q; }
    { ull q = __shfl_down_sync(0xFFFFFFFFu, p,  8); if (q > p) p = q; }
    if (lane == 0) {
        if (kb) atomicAdd(&blkkept, __popc(kb));
        atomicMax(&blkmax, p);
    }
    __syncthreads();
    if (tid == 0) {
        if (blkkept) atomicAdd(&g_kept, blkkept);
        else         atomicMax(&g_amax, blkmax);
    }
}

__device__ __forceinline__ bool edge_kept(int e, float w) {
    if (g_kept > 0) return (w > THRESH);
    int am = (int)(0xFFFFFFFFu - (unsigned)(g_amax & 0xFFFFFFFFull));
    return (e == am);
}

// ---------------- K3: mask + denoised weights + histogram ----------------
__global__ void k_mask(const int* __restrict__ ei, float* __restrict__ wout, int E) {
    int e = blockIdx.x * blockDim.x + threadIdx.x;
    if (e >= E) return;
    float w = g_w[e];
    bool keep = edge_kept(e, w);
    wout[e] = keep ? w : 0.0f;
    if (keep) atomicAdd(&g_cnt[ei[E + e]], 1);
}

// ---------------- K4a: dinv (deg = 1 + cnt) ----------------
__global__ void k_dinv() {
    int i = blockIdx.x * blockDim.x + threadIdx.x;
    if (i < NN) g_dinv[i] = rsqrtf(1.0f + (float)g_cnt[i]);
}

// ---------------- K4b: single-block scan ----------------
#define SCHUNK 40
__global__ void k_scan() {
    __shared__ int wsum[32];
    int t = threadIdx.x;
    int lane = t & 31, wid = t >> 5;
    int base = t * SCHUNK;
    int v[SCHUNK];
    int s = 0;
    #pragma unroll
    for (int i = 0; i < SCHUNK; i++) {
        int idx = base + i;
        v[i] = (idx < NN) ? g_cnt[idx] : 0;
        s += v[i];
    }
    int incl = s;
    #pragma unroll
    for (int o = 1; o < 32; o <<= 1) {
        int u = __shfl_up_sync(0xFFFFFFFFu, incl, o);
        if (lane >= o) incl += u;
    }
    if (lane == 31) wsum[wid] = incl;
    __syncthreads();
    if (wid == 0) {
        int ws = wsum[lane];
        #pragma unroll
        for (int o = 1; o < 32; o <<= 1) {
            int u = __shfl_up_sync(0xFFFFFFFFu, ws, o);
            if (lane >= o) ws += u;
        }
        wsum[lane] = ws;
    }
    __syncthreads();
    int excl = incl - s + (wid > 0 ? wsum[wid - 1] : 0);
    #pragma unroll
    for (int i = 0; i < SCHUNK; i++) {
        int idx = base + i;
        if (idx < NN) { g_off[idx] = excl; g_cur[idx] = excl; }
        excl += v[i];
    }
}

// ---------------- K5: CSR bucket fill ----------------
__global__ void k_fill(const int* __restrict__ ei, int E) {
    int e = blockIdx.x * blockDim.x + threadIdx.x;
    if (e >= E) return;
    float w = g_w[e];
    if (!edge_kept(e, w)) return;
    int s = ei[e], d = ei[E + e];
    int p = atomicAdd(&g_cur[d], 1);
    g_srcl[p] = s;
    g_coef[p] = g_dinv[s] * g_dinv[d];
}

// ---------------- K6: HMMA fp16 GEMM, 4-stage bulk pipeline -------------------
#define ASTR 40
#define STG_A 0
#define STG_B 10240
#define STG_SZ 20480
#define NSTG 4
#define GSMEM (NSTG * STG_SZ)   // 81920 B

__global__ void __launch_bounds__(256, 2) k_gemm_hmma() {
    extern __shared__ char smem[];
    __shared__ ull s_mbar[NSTG];
    uint32_t sb = s2u(smem);
    int tid = threadIdx.x, warp = tid >> 5, lane = tid & 31;
    int bx = blockIdx.x, by = blockIdx.y;
    int m0 = bx * 128, n0 = by * 128;
    int wm = warp >> 2, wn = warp & 3;

    int g = lane >> 3, r8 = lane & 7;
    uint32_t aoff = (uint32_t)((wm * 64 + (g & 1) * 8 + r8) * (ASTR * 2) + (g >> 1) * 16);
    uint32_t boff = (uint32_t)((wn * 32 + (g >> 1) * 8 + r8) * (ASTR * 2) + (g & 1) * 16);

    if (tid < NSTG) mbar_init(s2u(&s_mbar[tid]), 1);
    __syncthreads();

    float acc[4][4][4];
    #pragma unroll
    for (int i = 0; i < 4; i++)
        #pragma unroll
        for (int j = 0; j < 4; j++)
            #pragma unroll
            for (int q = 0; q < 4; q++) acc[i][j][q] = 0.f;

    auto issue_stage = [&](int c) {
        int stg = c & (NSTG - 1);
        uint32_t base = sb + (uint32_t)stg * STG_SZ;
        uint32_t mb = s2u(&s_mbar[stg]);
        mbar_expect(mb, STG_SZ);
        bulk_ld(base + STG_A, g_XT + ((size_t)bx * 8 + c) * TB, TB, mb);
        bulk_ld(base + STG_B, g_BT + ((size_t)by * 8 + c) * TB, TB, mb);
    };

    if (tid == 0) { issue_stage(0); issue_stage(1); issue_stage(2); }

    #pragma unroll 1
    for (int c = 0; c < 8; c++) {
        // buffer (c+3)&3 was drained at end of chunk c-1 (syncthreads), safe to reissue
        if (c + 3 < 8 && tid == 0) issue_stage(c + 3);
        mbar_wait(s2u(&s_mbar[c & (NSTG - 1)]), (uint32_t)((c >> 2) & 1));

        uint32_t base = sb + (uint32_t)(c & (NSTG - 1)) * STG_SZ;
        uint32_t sA = base + STG_A + aoff, sB = base + STG_B + boff;

        #pragma unroll
        for (int ks = 0; ks < 2; ks++) {
            uint32_t a[4][4], b[2][4];
            uint32_t kb = (uint32_t)(ks * 32);
            #pragma unroll
            for (int mf = 0; mf < 4; mf++) ldsm4(a[mf], sA + mf * (16 * ASTR * 2) + kb);
            #pragma unroll
            for (int j = 0; j < 2; j++) ldsm4(b[j], sB + j * (16 * ASTR * 2) + kb);
            #pragma unroll
            for (int mf = 0; mf < 4; mf++)
                #pragma unroll
                for (int j = 0; j < 2; j++) {
                    mma16816h(acc[mf][j*2+0], a[mf], &b[j][0]);
                    mma16816h(acc[mf][j*2+1], a[mf], &b[j][2]);
                }
        }
        __syncthreads();   // all warps done with this buffer before re-issue
    }

    int qr = lane >> 2, qc = (lane & 3) * 2;
    #pragma unroll
    for (int mf = 0; mf < 4; mf++) {
        int mrow = m0 + wm * 64 + mf * 16 + qr;
        #pragma unroll
        for (int nf = 0; nf < 4; nf++) {
            int col = n0 + wn * 32 + nf * 8 + qc;
            if (mrow < NN)
                *(float2*)&g_xw[(size_t)mrow * HID + col] = make_float2(acc[mf][nf][0], acc[mf][nf][1]);
            if (mrow + 8 < NN)
                *(float2*)&g_xw[(size_t)(mrow + 8) * HID + col] = make_float2(acc[mf][nf][2], acc[mf][nf][3]);
        }
    }
}

// ---------------- K7: per-node aggregate (sync-free, broadcast gather) --------
__global__ void k_agg(const float* __restrict__ bias, float* __restrict__ out) {
    int n = blockIdx.x, t = threadIdx.x;
    float di = g_dinv[n];
    float acc = g_xw[(size_t)n * HID + t] * (di * di) + bias[t];
    int beg = g_off[n], cnt = g_cnt[n];
    #pragma unroll 2
    for (int j = 0; j < cnt; j++) {
        int s = g_srcl[beg + j];          // warp-uniform broadcast load
        float cf = g_coef[beg + j];       // warp-uniform broadcast load
        acc += cf * g_xw[(size_t)s * HID + t];
    }
    out[(size_t)n * HID + t] = acc;
}

// ---------------- launch: fork/join overlap ----------------
extern "C" void kernel_launch(void* const* d_in, const int* in_sizes, int n_in,
                              void* d_out, int out_size) {
    const float* U  = (const float*)d_in[0];
    const float* I  = (const float*)d_in[1];
    const int*   ei = (const int*)  d_in[2];
    const float* W1 = (const float*)d_in[3];
    const float* b1 = (const float*)d_in[4];
    const float* W2 = (const float*)d_in[5];
    const float* b2 = (const float*)d_in[6];
    const float* GW = (const float*)d_in[7];
    const float* Gb = (const float*)d_in[8];
    int E = in_sizes[2] / 2;

    float* out  = (float*)d_out;
    float* wout = out + (size_t)NN * HID;

    static cudaStream_t s2 = nullptr;
    static cudaEvent_t evFork = nullptr, evJoin = nullptr;
    if (!s2) {
        cudaStreamCreateWithFlags(&s2, cudaStreamNonBlocking);
        cudaEventCreateWithFlags(&evFork, cudaEventDisableTiming);
        cudaEventCreateWithFlags(&evJoin, cudaEventDisableTiming);
        cudaFuncSetAttribute(k_gemm_hmma, cudaFuncAttributeMaxDynamicSharedMemorySize, GSMEM);
    }

    // fork: side stream runs the GEMM chain
    cudaEventRecord(evFork, 0);
    cudaStreamWaitEvent(s2, evFork, 0);
    k_prepW<<<HID * HID / 256, 256, 0, s2>>>(GW);
    k_prepX<<<(int)(((size_t)NN * HID / 4) / 256), 256, 0, s2>>>(U, I);
    k_gemm_hmma<<<dim3(MBLKS, HID / 128), 256, GSMEM, s2>>>();
    cudaEventRecord(evJoin, s2);

    // main stream: init -> proj -> edge -> mask -> dinv -> scan -> fill
    k_init<<<(NN + 255) / 256, 256>>>();
    k_projB<<<UB2 + IB2, 256>>>(U, I, W1, b1);
    k_edge<<<((E + 3) / 4 * 32 + 255) / 256, 256>>>(ei, W2, b2, E);
    k_mask<<<(E + 255) / 256, 256>>>(ei, wout, E);
    k_dinv<<<(NN + 255) / 256, 256>>>();
    k_scan<<<1, 1024>>>();
    k_fill<<<(E + 255) / 256, 256>>>(ei, E);

    // join: aggregate needs both g_xw and the CSR
    cudaStreamWaitEvent(0, evJoin, 0);
    k_agg<<<NN, 256>>>(Gb, out);
}